// round 1
// baseline (speedup 1.0000x reference)
#include <cuda_runtime.h>

#define Dd 2048
#define Mm 32
#define Hh 64
#define Bb 256

// ---- packed f32x2 FMA (FFMA2 in SASS; only reachable via PTX fma.rn.f32x2) ----
__device__ __forceinline__ unsigned long long pk2(float2 v) {
    unsigned long long r;
    asm("mov.b64 %0, {%1, %2};" : "=l"(r) : "f"(v.x), "f"(v.y));
    return r;
}
__device__ __forceinline__ float2 upk2(unsigned long long v) {
    float2 r;
    asm("mov.b64 {%0, %1}, %2;" : "=f"(r.x), "=f"(r.y) : "l"(v));
    return r;
}
__device__ __forceinline__ float2 ffma2(float2 a, float2 b, float2 c) {
    unsigned long long r;
    asm("fma.rn.f32x2 %0, %1, %2, %3;"
        : "=l"(r) : "l"(pk2(a)), "l"(pk2(b)), "l"(pk2(c)));
    return upk2(r);
}

// exact (erf) GELU, matching jax.nn.gelu(approximate=False)
__device__ __forceinline__ float geluf(float x) {
    return 0.5f * x * (1.0f + erff(x * 0.7071067811865476f));
}
__device__ __forceinline__ float2 gelu2(float2 v) {
    return make_float2(geluf(v.x), geluf(v.y));
}

__global__ void __launch_bounds__(128, 4)
neuron_mlp_kernel(const float* __restrict__ X,   // [B, D, M]
                  const float* __restrict__ W0,  // [D, M, H]
                  const float* __restrict__ b0,  // [D, H]
                  const float* __restrict__ W1,  // [D, H, H]
                  const float* __restrict__ b1,  // [D, H]
                  const float* __restrict__ W2,  // [D, H]
                  const float* __restrict__ b2,  // [D]
                  float* __restrict__ out)       // [B, D]
{
    __shared__ float sW0[Mm * Hh];     // 8 KB
    __shared__ float sW1[Hh * Hh];     // 16 KB
    __shared__ float sW2[Hh];
    __shared__ float sb0[Hh];
    __shared__ float sb1[Hh];
    __shared__ float sX[128 * 33];     // 16.5 KB, stride-33 pad (33 coprime 32)

    const int d  = blockIdx.x >> 1;
    const int bh = blockIdx.x & 1;     // batch half: rows [bh*128, bh*128+128)
    const int t  = threadIdx.x;        // 0..127, one batch row per thread

    // ---- cooperative, coalesced loads into smem ----
    {
        const float4* gW0 = (const float4*)(W0 + (size_t)d * (Mm * Hh));
        float4* s4 = (float4*)sW0;
        #pragma unroll
        for (int i = 0; i < 4; i++) s4[t + i * 128] = gW0[t + i * 128];
    }
    {
        const float4* gW1 = (const float4*)(W1 + (size_t)d * (Hh * Hh));
        float4* s4 = (float4*)sW1;
        #pragma unroll
        for (int i = 0; i < 8; i++) s4[t + i * 128] = gW1[t + i * 128];
    }
    if (t < 16) {
        ((float4*)sW2)[t] = ((const float4*)(W2 + (size_t)d * Hh))[t];
    } else if (t < 32) {
        ((float4*)sb0)[t - 16] = ((const float4*)(b0 + (size_t)d * Hh))[t - 16];
    } else if (t < 48) {
        ((float4*)sb1)[t - 32] = ((const float4*)(b1 + (size_t)d * Hh))[t - 32];
    }
    {
        // X rows for this (d, batch half): 128 rows x 32 floats, coalesced:
        // consecutive threads read consecutive m within a 128B row.
        const float* gX = X + (size_t)(bh * 128) * Dd * Mm + (size_t)d * Mm;
        #pragma unroll
        for (int k = 0; k < 32; k++) {
            int idx = t + k * 128;
            int r = idx >> 5;
            int m = idx & 31;
            sX[r * 33 + m] = gX[(size_t)r * (Dd * Mm) + m];
        }
    }
    __syncthreads();

    // ---- layer 0: h0[64] = gelu(x[32] @ W0 + b0), FFMA2 over output pairs ----
    float2 acc0[32];
    #pragma unroll
    for (int j = 0; j < 32; j++) acc0[j] = ((const float2*)sb0)[j];

    const float* xr = sX + t * 33;
    #pragma unroll
    for (int m = 0; m < Mm; m++) {
        float xv = xr[m];
        float2 xv2 = make_float2(xv, xv);
        const float4* w = (const float4*)(sW0 + m * Hh);
        #pragma unroll
        for (int j = 0; j < 16; j++) {
            float4 wv = w[j];                       // broadcast LDS.128
            acc0[2 * j]     = ffma2(make_float2(wv.x, wv.y), xv2, acc0[2 * j]);
            acc0[2 * j + 1] = ffma2(make_float2(wv.z, wv.w), xv2, acc0[2 * j + 1]);
        }
    }
    #pragma unroll
    for (int j = 0; j < 32; j++) acc0[j] = gelu2(acc0[j]);

    // ---- layer 1 (64x64) in two 32-output halves (register pressure) +
    //      layer 2 dot folded into each half's epilogue ----
    float2 ores = make_float2(0.0f, 0.0f);
    #pragma unroll 1
    for (int half = 0; half < 2; half++) {
        float2 acc1[16];
        const float2* sb1h = (const float2*)sb1 + half * 16;
        #pragma unroll
        for (int j = 0; j < 16; j++) acc1[j] = sb1h[j];

        const float* w1base = sW1 + half * 32;
        #pragma unroll
        for (int hp = 0; hp < 32; hp++) {
            float2 a  = acc0[hp];
            float2 ax = make_float2(a.x, a.x);
            float2 ay = make_float2(a.y, a.y);
            const float4* w0r = (const float4*)(w1base + (2 * hp) * Hh);
            const float4* w1r = (const float4*)(w1base + (2 * hp + 1) * Hh);
            #pragma unroll
            for (int j = 0; j < 8; j++) {
                float4 wv = w0r[j];
                acc1[2 * j]     = ffma2(make_float2(wv.x, wv.y), ax, acc1[2 * j]);
                acc1[2 * j + 1] = ffma2(make_float2(wv.z, wv.w), ax, acc1[2 * j + 1]);
                wv = w1r[j];
                acc1[2 * j]     = ffma2(make_float2(wv.x, wv.y), ay, acc1[2 * j]);
                acc1[2 * j + 1] = ffma2(make_float2(wv.z, wv.w), ay, acc1[2 * j + 1]);
            }
        }
        const float2* w2h = (const float2*)sW2 + half * 16;
        #pragma unroll
        for (int j = 0; j < 16; j++) {
            float2 g = gelu2(acc1[j]);
            ores = ffma2(g, w2h[j], ores);
        }
    }

    float res = ores.x + ores.y + b2[d];
    int b = bh * 128 + t;
    out[(size_t)b * Dd + d] = res;
}

extern "C" void kernel_launch(void* const* d_in, const int* in_sizes, int n_in,
                              void* d_out, int out_size) {
    const float* X  = (const float*)d_in[0];
    const float* W0 = (const float*)d_in[1];
    const float* b0 = (const float*)d_in[2];
    const float* W1 = (const float*)d_in[3];
    const float* b1 = (const float*)d_in[4];
    const float* W2 = (const float*)d_in[5];
    const float* b2 = (const float*)d_in[6];
    float* out = (float*)d_out;

    neuron_mlp_kernel<<<Dd * 2, 128>>>(X, W0, b0, W1, b1, W2, b2, out);
}